// round 1
// baseline (speedup 1.0000x reference)
#include <cuda_runtime.h>
#include <cuda_bf16.h>
#include <cstdint>
#include <cstddef>

#define N_QTOK 4096      // 128 query batches * 32 tokens
#define N_DTOK 16384     // 128 doc batches * 128 tokens
#define N_TOK  20480
#define DIM    128
#define HID    256

// bf16 normalized embeddings: rows 0..4095 = query tokens, 4096..20479 = doc tokens
__device__ __nv_bfloat16 g_emb[(size_t)N_TOK * DIM];

// ---------------------------------------------------------------------------
// Kernel 1: token_mapper projection + bias + L2 normalize (fp32 math, bf16 out)
// One block = 32 token rows. C tile 32x128, K tiled by 64 through smem.
// ---------------------------------------------------------------------------
__global__ __launch_bounds__(256) void embed_kernel(
    const float* __restrict__ qh, const float* __restrict__ dh,
    const float* __restrict__ W, const float* __restrict__ bias)
{
    __shared__ float hs[32 * 68];    // 32 rows x 64 k (pad to 68)
    __shared__ float Ws[64 * 132];   // 64 k x 128 d (pad to 132)

    const int tid  = threadIdx.x;
    const int row0 = blockIdx.x * 32;
    const float* src = (row0 < N_QTOK) ? (qh + (size_t)row0 * HID)
                                       : (dh + (size_t)(row0 - N_QTOK) * HID);

    float acc0[8], acc1[8];
#pragma unroll
    for (int j = 0; j < 8; j++) { acc0[j] = 0.f; acc1[j] = 0.f; }

    const int p  = tid >> 4;     // token pair 0..15 (tokens 2p, 2p+1)
    const int c  = tid & 15;     // column group
    const int d0 = c * 8;

    for (int kt = 0; kt < 4; kt++) {
        const int k0 = kt * 64;
        __syncthreads();
        // load h tile: 32x64 floats = 512 float4
#pragma unroll
        for (int j = 0; j < 2; j++) {
            int f = tid + j * 256;
            int r = f >> 4, cv = f & 15;
            *(float4*)&hs[r * 68 + cv * 4] =
                *(const float4*)(src + (size_t)r * HID + k0 + cv * 4);
        }
        // load W tile: 64x128 floats = 2048 float4
#pragma unroll
        for (int j = 0; j < 8; j++) {
            int f = tid + j * 256;
            int r = f >> 5, cv = f & 31;
            *(float4*)&Ws[r * 132 + cv * 4] =
                *(const float4*)(W + (size_t)(k0 + r) * DIM + cv * 4);
        }
        __syncthreads();
#pragma unroll 8
        for (int k = 0; k < 64; k++) {
            float h0 = hs[(2 * p) * 68 + k];
            float h1 = hs[(2 * p + 1) * 68 + k];
            float4 w0 = *(const float4*)&Ws[k * 132 + d0];
            float4 w1 = *(const float4*)&Ws[k * 132 + d0 + 4];
            acc0[0] += h0 * w0.x; acc0[1] += h0 * w0.y;
            acc0[2] += h0 * w0.z; acc0[3] += h0 * w0.w;
            acc0[4] += h0 * w1.x; acc0[5] += h0 * w1.y;
            acc0[6] += h0 * w1.z; acc0[7] += h0 * w1.w;
            acc1[0] += h1 * w0.x; acc1[1] += h1 * w0.y;
            acc1[2] += h1 * w0.z; acc1[3] += h1 * w0.w;
            acc1[4] += h1 * w1.x; acc1[5] += h1 * w1.y;
            acc1[6] += h1 * w1.z; acc1[7] += h1 * w1.w;
        }
    }

    // bias + sum of squares
    float4 b0 = *(const float4*)(bias + d0);
    float4 b1 = *(const float4*)(bias + d0 + 4);
    float bb[8] = { b0.x, b0.y, b0.z, b0.w, b1.x, b1.y, b1.z, b1.w };
    float ss0 = 0.f, ss1 = 0.f;
#pragma unroll
    for (int j = 0; j < 8; j++) {
        acc0[j] += bb[j]; acc1[j] += bb[j];
        ss0 += acc0[j] * acc0[j]; ss1 += acc1[j] * acc1[j];
    }
    // reduce over the 16 threads sharing a token pair (xor 1,2,4,8 stays in-group)
#pragma unroll
    for (int off = 8; off >= 1; off >>= 1) {
        ss0 += __shfl_xor_sync(0xffffffffu, ss0, off);
        ss1 += __shfl_xor_sync(0xffffffffu, ss1, off);
    }
    float inv0 = 1.f / fmaxf(sqrtf(ss0), 1e-12f);
    float inv1 = 1.f / fmaxf(sqrtf(ss1), 1e-12f);

    __nv_bfloat16* o0 = g_emb + (size_t)(row0 + 2 * p) * DIM + d0;
    __nv_bfloat16* o1 = o0 + DIM;
#pragma unroll
    for (int j = 0; j < 8; j++) {
        o0[j] = __float2bfloat16(acc0[j] * inv0);
        o1[j] = __float2bfloat16(acc1[j] * inv1);
    }
}

// ---------------------------------------------------------------------------
// Kernel 2: fused similarity GEMM (bf16 mma.sync m16n8k16) + max_t + sum_s
// Block = 256 threads (8 warps, 2x4), tile M=64 (2 query batches) x N=128
// (one doc batch), K=128. Loops over 16 doc batches, cp.async double-buffered.
// ---------------------------------------------------------------------------
#define DSTR      136                 // padded bf16 row stride (conflict-free)
#define QROWS     64
#define DBUF_ELEM (128 * DSTR)

__device__ __forceinline__ void cp_async16(unsigned saddr, const void* g) {
    asm volatile("cp.async.cg.shared.global [%0], [%1], 16;\n"
                 :: "r"(saddr), "l"(g) : "memory");
}
__device__ __forceinline__ void cp_commit() {
    asm volatile("cp.async.commit_group;\n" ::: "memory");
}
template <int N> __device__ __forceinline__ void cp_wait() {
    asm volatile("cp.async.wait_group %0;\n" :: "n"(N) : "memory");
}
__device__ __forceinline__ void ldsm4(uint32_t& r0, uint32_t& r1,
                                      uint32_t& r2, uint32_t& r3, unsigned addr) {
    asm volatile("ldmatrix.sync.aligned.m8n8.x4.shared.b16 {%0,%1,%2,%3}, [%4];\n"
                 : "=r"(r0), "=r"(r1), "=r"(r2), "=r"(r3) : "r"(addr));
}
__device__ __forceinline__ void mma16816(float* c, const uint32_t* a,
                                         uint32_t b0, uint32_t b1) {
    asm volatile(
        "mma.sync.aligned.m16n8k16.row.col.f32.bf16.bf16.f32 "
        "{%0,%1,%2,%3}, {%4,%5,%6,%7}, {%8,%9}, {%0,%1,%2,%3};\n"
        : "+f"(c[0]), "+f"(c[1]), "+f"(c[2]), "+f"(c[3])
        : "r"(a[0]), "r"(a[1]), "r"(a[2]), "r"(a[3]), "r"(b0), "r"(b1));
}

__global__ __launch_bounds__(256) void sim_kernel(float* __restrict__ out)
{
    extern __shared__ char smem[];
    __nv_bfloat16* sQ = (__nv_bfloat16*)smem;             // 64 x 136
    __nv_bfloat16* sD = sQ + QROWS * DSTR;                // 2 x (128 x 136)
    float* red = (float*)(sD + 2 * DBUF_ELEM);            // [64][4]

    const int tid  = threadIdx.x;
    const int lane = tid & 31, warp = tid >> 5;
    const int mw = warp >> 2, nw = warp & 3;
    const int qp  = blockIdx.y;          // query-batch pair 0..63
    const int db0 = blockIdx.x * 16;     // first doc batch of this chunk

    // load Q tile (64 query-token rows)
    {
        const __nv_bfloat16* qsrc = g_emb + (size_t)qp * QROWS * DIM;
#pragma unroll
        for (int j = 0; j < 4; j++) {
            int f = tid + j * 256;
            int r = f >> 4, cv = f & 15;
            *(uint4*)(sQ + r * DSTR + cv * 8) =
                *(const uint4*)(qsrc + (size_t)r * DIM + cv * 8);
        }
    }

    const unsigned sQb = (unsigned)__cvta_generic_to_shared(sQ);
    const unsigned sDb = (unsigned)__cvta_generic_to_shared(sD);

    // prefetch first doc tile into buffer 0
    {
        const __nv_bfloat16* dsrc = g_emb + (size_t)(N_QTOK + db0 * 128) * DIM;
#pragma unroll
        for (int j = 0; j < 8; j++) {
            int f = tid + j * 256;
            int r = f >> 4, cv = f & 15;
            cp_async16(sDb + (unsigned)(r * DSTR + cv * 8) * 2,
                       dsrc + (size_t)r * DIM + cv * 8);
        }
        cp_commit();
    }

    // ldmatrix per-thread address components (canonical m16n8k16 mapping)
    unsigned aoff[2], boffr[2];
#pragma unroll
    for (int mt = 0; mt < 2; mt++) {
        int row = mw * 32 + mt * 16 + (lane & 7) + ((lane >> 3) & 1) * 8;
        int col = (lane >> 4) * 8;
        aoff[mt] = sQb + (unsigned)(row * DSTR + col) * 2;
    }
#pragma unroll
    for (int ng = 0; ng < 2; ng++) {
        int row = nw * 32 + ng * 16 + (lane & 7) + (lane >> 4) * 8;
        int col = ((lane >> 3) & 1) * 8;
        boffr[ng] = (unsigned)(row * DSTR + col) * 2;
    }

    for (int i = 0; i < 16; i++) {
        const int cur = i & 1;
        if (i + 1 < 16) {   // prefetch next tile into alternate buffer
            const __nv_bfloat16* dsrc =
                g_emb + (size_t)(N_QTOK + (db0 + i + 1) * 128) * DIM;
            unsigned dst = sDb + (unsigned)((i + 1) & 1) * (DBUF_ELEM * 2);
#pragma unroll
            for (int j = 0; j < 8; j++) {
                int f = tid + j * 256;
                int r = f >> 4, cv = f & 15;
                cp_async16(dst + (unsigned)(r * DSTR + cv * 8) * 2,
                           dsrc + (size_t)r * DIM + cv * 8);
            }
            cp_commit();
            cp_wait<1>();   // current buffer's group drained
        } else {
            cp_wait<0>();
        }
        __syncthreads();

        float acc[2][4][4];
#pragma unroll
        for (int mt = 0; mt < 2; mt++)
#pragma unroll
            for (int nt = 0; nt < 4; nt++)
#pragma unroll
                for (int r = 0; r < 4; r++) acc[mt][nt][r] = 0.f;

        const unsigned dbase = sDb + (unsigned)cur * (DBUF_ELEM * 2);
#pragma unroll
        for (int ks = 0; ks < 8; ks++) {
            uint32_t a[2][4], bfr[2][4];
            ldsm4(a[0][0], a[0][1], a[0][2], a[0][3], aoff[0] + ks * 32);
            ldsm4(a[1][0], a[1][1], a[1][2], a[1][3], aoff[1] + ks * 32);
            ldsm4(bfr[0][0], bfr[0][1], bfr[0][2], bfr[0][3],
                  dbase + boffr[0] + ks * 32);
            ldsm4(bfr[1][0], bfr[1][1], bfr[1][2], bfr[1][3],
                  dbase + boffr[1] + ks * 32);
#pragma unroll
            for (int mt = 0; mt < 2; mt++) {
                mma16816(acc[mt][0], a[mt], bfr[0][0], bfr[0][1]);
                mma16816(acc[mt][1], a[mt], bfr[0][2], bfr[0][3]);
                mma16816(acc[mt][2], a[mt], bfr[1][0], bfr[1][1]);
                mma16816(acc[mt][3], a[mt], bfr[1][2], bfr[1][3]);
            }
        }

        // epilogue: max over doc tokens (columns), then sum over query tokens
#pragma unroll
        for (int mt = 0; mt < 2; mt++) {
#pragma unroll
            for (int h = 0; h < 2; h++) {
                float m = -3.4e38f;
#pragma unroll
                for (int nt = 0; nt < 4; nt++)
                    m = fmaxf(m, fmaxf(acc[mt][nt][2 * h], acc[mt][nt][2 * h + 1]));
                m = fmaxf(m, __shfl_xor_sync(0xffffffffu, m, 1));
                m = fmaxf(m, __shfl_xor_sync(0xffffffffu, m, 2));
                if ((lane & 3) == 0)
                    red[(mw * 32 + mt * 16 + h * 8 + (lane >> 2)) * 4 + nw] = m;
            }
        }
        __syncthreads();
        if (tid < 64) {   // warps 0,1 handle query batches qp*2, qp*2+1
            float rm = fmaxf(fmaxf(red[tid * 4 + 0], red[tid * 4 + 1]),
                             fmaxf(red[tid * 4 + 2], red[tid * 4 + 3]));
#pragma unroll
            for (int off = 16; off >= 1; off >>= 1)
                rm += __shfl_xor_sync(0xffffffffu, rm, off);
            if (lane == 0)
                out[(size_t)(qp * 2 + warp) * 128 + (db0 + i)] = rm;
        }
        __syncthreads();   // guard red[] + d-buffer reuse
    }
}

// ---------------------------------------------------------------------------
extern "C" void kernel_launch(void* const* d_in, const int* in_sizes, int n_in,
                              void* d_out, int out_size) {
    const float* qh   = (const float*)d_in[0];
    const float* dh   = (const float*)d_in[1];
    const float* W    = (const float*)d_in[2];
    const float* bias = (const float*)d_in[3];
    float* out = (float*)d_out;

    const int SMEM = QROWS * DSTR * 2 + 2 * DBUF_ELEM * 2 + 64 * 4 * 4; // 88064 B
    cudaFuncSetAttribute(sim_kernel,
                         cudaFuncAttributeMaxDynamicSharedMemorySize, SMEM);

    embed_kernel<<<N_TOK / 32, 256>>>(qh, dh, W, bias);
    sim_kernel<<<dim3(8, 64), 256, SMEM>>>(out);
}

// round 2
// speedup vs baseline: 1.7869x; 1.7869x over previous
#include <cuda_runtime.h>
#include <cuda_bf16.h>
#include <cstdint>
#include <cstddef>

#define N_QTOK 4096      // 128 query batches * 32 tokens
#define N_DTOK 16384     // 128 doc batches * 128 tokens
#define N_TOK  20480
#define DIM    128
#define HID    256

// bf16 normalized embeddings: rows 0..4095 = query tokens, 4096..20479 = doc tokens
__device__ __nv_bfloat16 g_emb[(size_t)N_TOK * DIM];

// ---------------------------------------------------------------------------
// shared PTX helpers
// ---------------------------------------------------------------------------
__device__ __forceinline__ void ldsm4(uint32_t& r0, uint32_t& r1,
                                      uint32_t& r2, uint32_t& r3, unsigned addr) {
    asm volatile("ldmatrix.sync.aligned.m8n8.x4.shared.b16 {%0,%1,%2,%3}, [%4];\n"
                 : "=r"(r0), "=r"(r1), "=r"(r2), "=r"(r3) : "r"(addr));
}
__device__ __forceinline__ void ldsm4t(uint32_t& r0, uint32_t& r1,
                                       uint32_t& r2, uint32_t& r3, unsigned addr) {
    asm volatile("ldmatrix.sync.aligned.m8n8.x4.trans.shared.b16 {%0,%1,%2,%3}, [%4];\n"
                 : "=r"(r0), "=r"(r1), "=r"(r2), "=r"(r3) : "r"(addr));
}
__device__ __forceinline__ void mma16816(float* c, const uint32_t* a,
                                         uint32_t b0, uint32_t b1) {
    asm volatile(
        "mma.sync.aligned.m16n8k16.row.col.f32.bf16.bf16.f32 "
        "{%0,%1,%2,%3}, {%4,%5,%6,%7}, {%8,%9}, {%0,%1,%2,%3};\n"
        : "+f"(c[0]), "+f"(c[1]), "+f"(c[2]), "+f"(c[3])
        : "r"(a[0]), "r"(a[1]), "r"(a[2]), "r"(a[3]), "r"(b0), "r"(b1));
}
__device__ __forceinline__ void cp_async16(unsigned saddr, const void* g) {
    asm volatile("cp.async.cg.shared.global [%0], [%1], 16;\n"
                 :: "r"(saddr), "l"(g) : "memory");
}
__device__ __forceinline__ void cp_commit() {
    asm volatile("cp.async.commit_group;\n" ::: "memory");
}
template <int N> __device__ __forceinline__ void cp_wait() {
    asm volatile("cp.async.wait_group %0;\n" :: "n"(N) : "memory");
}

// ---------------------------------------------------------------------------
// Kernel 1: projection + bias + L2 normalize via tensor cores.
// fp32 inputs split into bf16 hi+lo; C = Ahi*Bhi + Ahi*Blo + Alo*Bhi (fp32 acc)
// gives ~2^-18 relative accuracy (effectively fp32).
// Block = 256 thr (8 warps); tile M=128 rows x N=128, K looped in 64-chunks.
// Each warp: 16 rows x full N=128.
// ---------------------------------------------------------------------------
#define KPAD 72     // A smem k-stride (bf16 elems): 144B row pitch, conflict-free
#define NPAD 136    // W smem n-stride: 272B row pitch, conflict-free

__global__ __launch_bounds__(256, 2) void embed_kernel(
    const float* __restrict__ qh, const float* __restrict__ dh,
    const float* __restrict__ W, const float* __restrict__ bias)
{
    extern __shared__ char esm[];
    __nv_bfloat16* sAhi = (__nv_bfloat16*)esm;              // 128 x 72
    __nv_bfloat16* sAlo = sAhi + 128 * KPAD;
    __nv_bfloat16* sWhi = sAlo + 128 * KPAD;                // 64 x 136
    __nv_bfloat16* sWlo = sWhi + 64 * NPAD;

    const int tid  = threadIdx.x;
    const int lane = tid & 31, warp = tid >> 5;
    const int row0 = blockIdx.x * 128;
    const float* src = (row0 < N_QTOK) ? (qh + (size_t)row0 * HID)
                                       : (dh + (size_t)(row0 - N_QTOK) * HID);

    float acc[16][4];
#pragma unroll
    for (int nt = 0; nt < 16; nt++)
#pragma unroll
        for (int r = 0; r < 4; r++) acc[nt][r] = 0.f;

    const unsigned uAhi = (unsigned)__cvta_generic_to_shared(sAhi);
    const unsigned uAlo = (unsigned)__cvta_generic_to_shared(sAlo);
    const unsigned uWhi = (unsigned)__cvta_generic_to_shared(sWhi);
    const unsigned uWlo = (unsigned)__cvta_generic_to_shared(sWlo);

    // A ldmatrix (row-major M x K): lanes 0-15 rows, 16-31 rows at k+8
    const unsigned aoff =
        (unsigned)((warp * 16 + (lane & 15)) * KPAD + (lane >> 4) * 8) * 2;
    // B ldmatrix.trans (row-major K x N)
    const int bk = (lane & 7) + ((lane >> 3) & 1) * 8;
    const int bn = (lane >> 4) * 8;

    for (int kc = 0; kc < 4; kc++) {
        const int k0 = kc * 64;
        __syncthreads();
        // X chunk: 128 x 64 fp32 -> hi/lo bf16 (8 float4 per thread)
#pragma unroll
        for (int j = 0; j < 8; j++) {
            int f = tid + j * 256, r = f >> 4, cv = f & 15;
            float4 v = *(const float4*)(src + (size_t)r * HID + k0 + cv * 4);
            __nv_bfloat16 h[4], l[4];
            float vv[4] = { v.x, v.y, v.z, v.w };
#pragma unroll
            for (int e = 0; e < 4; e++) {
                h[e] = __float2bfloat16(vv[e]);
                l[e] = __float2bfloat16(vv[e] - __bfloat162float(h[e]));
            }
            *(uint2*)&sAhi[r * KPAD + cv * 4] = *(uint2*)h;
            *(uint2*)&sAlo[r * KPAD + cv * 4] = *(uint2*)l;
        }
        // W chunk: 64 x 128 fp32 -> hi/lo bf16 (8 float4 per thread)
#pragma unroll
        for (int j = 0; j < 8; j++) {
            int f = tid + j * 256, r = f >> 5, cv = f & 31;
            float4 v = *(const float4*)(W + (size_t)(k0 + r) * DIM + cv * 4);
            __nv_bfloat16 h[4], l[4];
            float vv[4] = { v.x, v.y, v.z, v.w };
#pragma unroll
            for (int e = 0; e < 4; e++) {
                h[e] = __float2bfloat16(vv[e]);
                l[e] = __float2bfloat16(vv[e] - __bfloat162float(h[e]));
            }
            *(uint2*)&sWhi[r * NPAD + cv * 4] = *(uint2*)h;
            *(uint2*)&sWlo[r * NPAD + cv * 4] = *(uint2*)l;
        }
        __syncthreads();

#pragma unroll
        for (int ks = 0; ks < 4; ks++) {
            uint32_t ah[4], al[4];
            ldsm4(ah[0], ah[1], ah[2], ah[3], uAhi + aoff + ks * 32);
            ldsm4(al[0], al[1], al[2], al[3], uAlo + aoff + ks * 32);
            const unsigned brow = (unsigned)((ks * 16 + bk) * NPAD + bn) * 2;
#pragma unroll
            for (int ntp = 0; ntp < 8; ntp++) {
                uint32_t bh[4], bl[4];
                ldsm4t(bh[0], bh[1], bh[2], bh[3], uWhi + brow + ntp * 32);
                ldsm4t(bl[0], bl[1], bl[2], bl[3], uWlo + brow + ntp * 32);
                mma16816(acc[2 * ntp],     ah, bh[0], bh[1]);
                mma16816(acc[2 * ntp],     ah, bl[0], bl[1]);
                mma16816(acc[2 * ntp],     al, bh[0], bh[1]);
                mma16816(acc[2 * ntp + 1], ah, bh[2], bh[3]);
                mma16816(acc[2 * ntp + 1], ah, bl[2], bl[3]);
                mma16816(acc[2 * ntp + 1], al, bh[2], bh[3]);
            }
        }
    }

    // epilogue: bias, L2 norm per row, bf16 store
    const int cbase = (lane & 3) * 2;
    float ssA = 0.f, ssB = 0.f;
#pragma unroll
    for (int nt = 0; nt < 16; nt++) {
        float2 bv = *(const float2*)(bias + nt * 8 + cbase);
        acc[nt][0] += bv.x; acc[nt][1] += bv.y;
        acc[nt][2] += bv.x; acc[nt][3] += bv.y;
        ssA += acc[nt][0] * acc[nt][0] + acc[nt][1] * acc[nt][1];
        ssB += acc[nt][2] * acc[nt][2] + acc[nt][3] * acc[nt][3];
    }
    ssA += __shfl_xor_sync(0xffffffffu, ssA, 1);
    ssA += __shfl_xor_sync(0xffffffffu, ssA, 2);
    ssB += __shfl_xor_sync(0xffffffffu, ssB, 1);
    ssB += __shfl_xor_sync(0xffffffffu, ssB, 2);
    float invA = 1.f / fmaxf(sqrtf(ssA), 1e-12f);
    float invB = 1.f / fmaxf(sqrtf(ssB), 1e-12f);

    const int rA = row0 + warp * 16 + (lane >> 2);
    const int rB = rA + 8;
#pragma unroll
    for (int nt = 0; nt < 16; nt++) {
        __nv_bfloat162 vA, vB;
        vA.x = __float2bfloat16(acc[nt][0] * invA);
        vA.y = __float2bfloat16(acc[nt][1] * invA);
        vB.x = __float2bfloat16(acc[nt][2] * invB);
        vB.y = __float2bfloat16(acc[nt][3] * invB);
        *(__nv_bfloat162*)(g_emb + (size_t)rA * DIM + nt * 8 + cbase) = vA;
        *(__nv_bfloat162*)(g_emb + (size_t)rB * DIM + nt * 8 + cbase) = vB;
    }
}

// ---------------------------------------------------------------------------
// Kernel 2: fused similarity GEMM (bf16 mma m16n8k16) + max_t + sum_s
// Block = 256 thr (8 warps, 2x4), tile M=64 x N=128 (one doc batch), K=128.
// 16 doc batches per block, cp.async double-buffered smem +
// register double-buffered ldmatrix (software pipeline over k-steps).
// ---------------------------------------------------------------------------
#define DSTR      136
#define QROWS     64
#define DBUF_ELEM (128 * DSTR)

__global__ __launch_bounds__(256) void sim_kernel(float* __restrict__ out)
{
    extern __shared__ char smem[];
    __nv_bfloat16* sQ = (__nv_bfloat16*)smem;             // 64 x 136
    __nv_bfloat16* sD = sQ + QROWS * DSTR;                // 2 x (128 x 136)
    float* red = (float*)(sD + 2 * DBUF_ELEM);            // [64][4]

    const int tid  = threadIdx.x;
    const int lane = tid & 31, warp = tid >> 5;
    const int mw = warp >> 2, nw = warp & 3;
    const int qp  = blockIdx.y;          // query-batch pair 0..63
    const int db0 = blockIdx.x * 16;     // first doc batch of this chunk

    {   // load Q tile (64 query-token rows)
        const __nv_bfloat16* qsrc = g_emb + (size_t)qp * QROWS * DIM;
#pragma unroll
        for (int j = 0; j < 4; j++) {
            int f = tid + j * 256;
            int r = f >> 4, cv = f & 15;
            *(uint4*)(sQ + r * DSTR + cv * 8) =
                *(const uint4*)(qsrc + (size_t)r * DIM + cv * 8);
        }
    }

    const unsigned sQb = (unsigned)__cvta_generic_to_shared(sQ);
    const unsigned sDb = (unsigned)__cvta_generic_to_shared(sD);

    {   // prefetch first doc tile into buffer 0
        const __nv_bfloat16* dsrc = g_emb + (size_t)(N_QTOK + db0 * 128) * DIM;
#pragma unroll
        for (int j = 0; j < 8; j++) {
            int f = tid + j * 256;
            int r = f >> 4, cv = f & 15;
            cp_async16(sDb + (unsigned)(r * DSTR + cv * 8) * 2,
                       dsrc + (size_t)r * DIM + cv * 8);
        }
        cp_commit();
    }

    unsigned aoff[2], boffr[2];
#pragma unroll
    for (int mt = 0; mt < 2; mt++) {
        int row = mw * 32 + mt * 16 + (lane & 15);
        int col = (lane >> 4) * 8;
        aoff[mt] = sQb + (unsigned)(row * DSTR + col) * 2;
    }
#pragma unroll
    for (int ng = 0; ng < 2; ng++) {
        int row = nw * 32 + ng * 16 + (lane & 7) + (lane >> 4) * 8;
        int col = ((lane >> 3) & 1) * 8;
        boffr[ng] = (unsigned)(row * DSTR + col) * 2;
    }

    for (int i = 0; i < 16; i++) {
        const int cur = i & 1;
        if (i + 1 < 16) {   // prefetch next tile into alternate buffer
            const __nv_bfloat16* dsrc =
                g_emb + (size_t)(N_QTOK + (db0 + i + 1) * 128) * DIM;
            unsigned dst = sDb + (unsigned)((i + 1) & 1) * (DBUF_ELEM * 2);
#pragma unroll
            for (int j = 0; j < 8; j++) {
                int f = tid + j * 256;
                int r = f >> 4, cv = f & 15;
                cp_async16(dst + (unsigned)(r * DSTR + cv * 8) * 2,
                           dsrc + (size_t)r * DIM + cv * 8);
            }
            cp_commit();
            cp_wait<1>();
        } else {
            cp_wait<0>();
        }
        __syncthreads();

        float acc[2][4][4];
#pragma unroll
        for (int mt = 0; mt < 2; mt++)
#pragma unroll
            for (int nt = 0; nt < 4; nt++)
#pragma unroll
                for (int r = 0; r < 4; r++) acc[mt][nt][r] = 0.f;

        const unsigned dbase = sDb + (unsigned)cur * (DBUF_ELEM * 2);

        // software-pipelined k loop: ldsm for ks+1 issued before mma on ks
        uint32_t a[2][2][4], b[2][2][4];
        ldsm4(a[0][0][0], a[0][0][1], a[0][0][2], a[0][0][3], aoff[0]);
        ldsm4(a[0][1][0], a[0][1][1], a[0][1][2], a[0][1][3], aoff[1]);
        ldsm4(b[0][0][0], b[0][0][1], b[0][0][2], b[0][0][3], dbase + boffr[0]);
        ldsm4(b[0][1][0], b[0][1][1], b[0][1][2], b[0][1][3], dbase + boffr[1]);
#pragma unroll
        for (int ks = 0; ks < 8; ks++) {
            const int cu = ks & 1, nx = cu ^ 1;
            if (ks < 7) {
                ldsm4(a[nx][0][0], a[nx][0][1], a[nx][0][2], a[nx][0][3],
                      aoff[0] + (ks + 1) * 32);
                ldsm4(a[nx][1][0], a[nx][1][1], a[nx][1][2], a[nx][1][3],
                      aoff[1] + (ks + 1) * 32);
                ldsm4(b[nx][0][0], b[nx][0][1], b[nx][0][2], b[nx][0][3],
                      dbase + boffr[0] + (ks + 1) * 32);
                ldsm4(b[nx][1][0], b[nx][1][1], b[nx][1][2], b[nx][1][3],
                      dbase + boffr[1] + (ks + 1) * 32);
            }
#pragma unroll
            for (int mt = 0; mt < 2; mt++) {
                mma16816(acc[mt][0], a[cu][mt], b[cu][0][0], b[cu][0][1]);
                mma16816(acc[mt][1], a[cu][mt], b[cu][0][2], b[cu][0][3]);
                mma16816(acc[mt][2], a[cu][mt], b[cu][1][0], b[cu][1][1]);
                mma16816(acc[mt][3], a[cu][mt], b[cu][1][2], b[cu][1][3]);
            }
        }

        // epilogue: max over doc tokens (columns), then sum over query tokens
#pragma unroll
        for (int mt = 0; mt < 2; mt++) {
#pragma unroll
            for (int h = 0; h < 2; h++) {
                float m = -3.4e38f;
#pragma unroll
                for (int nt = 0; nt < 4; nt++)
                    m = fmaxf(m, fmaxf(acc[mt][nt][2 * h], acc[mt][nt][2 * h + 1]));
                m = fmaxf(m, __shfl_xor_sync(0xffffffffu, m, 1));
                m = fmaxf(m, __shfl_xor_sync(0xffffffffu, m, 2));
                if ((lane & 3) == 0)
                    red[(mw * 32 + mt * 16 + h * 8 + (lane >> 2)) * 4 + nw] = m;
            }
        }
        __syncthreads();
        if (tid < 64) {
            float rm = fmaxf(fmaxf(red[tid * 4 + 0], red[tid * 4 + 1]),
                             fmaxf(red[tid * 4 + 2], red[tid * 4 + 3]));
#pragma unroll
            for (int off = 16; off >= 1; off >>= 1)
                rm += __shfl_xor_sync(0xffffffffu, rm, off);
            if (lane == 0)
                out[(size_t)(qp * 2 + warp) * 128 + (db0 + i)] = rm;
        }
        __syncthreads();
    }
}

// ---------------------------------------------------------------------------
extern "C" void kernel_launch(void* const* d_in, const int* in_sizes, int n_in,
                              void* d_out, int out_size) {
    const float* qh   = (const float*)d_in[0];
    const float* dh   = (const float*)d_in[1];
    const float* W    = (const float*)d_in[2];
    const float* bias = (const float*)d_in[3];
    float* out = (float*)d_out;

    const int ESMEM = (128 * KPAD * 2 + 64 * NPAD * 2) * 2;               // 71680
    const int SSMEM = QROWS * DSTR * 2 + 2 * DBUF_ELEM * 2 + 64 * 4 * 4;  // 88064
    cudaFuncSetAttribute(embed_kernel,
                         cudaFuncAttributeMaxDynamicSharedMemorySize, ESMEM);
    cudaFuncSetAttribute(sim_kernel,
                         cudaFuncAttributeMaxDynamicSharedMemorySize, SSMEM);

    embed_kernel<<<N_TOK / 128, 256, ESMEM>>>(qh, dh, W, bias);
    sim_kernel<<<dim3(8, 64), 256, SSMEM>>>(out);
}

// round 4
// speedup vs baseline: 2.1297x; 1.1918x over previous
#include <cuda_runtime.h>
#include <cuda_bf16.h>
#include <cstdint>
#include <cstddef>

#define N_QTOK 4096      // 128 query batches * 32 tokens
#define N_DTOK 16384     // 128 doc batches * 128 tokens
#define N_TOK  20480
#define DIM    128
#define HID    256

// bf16 normalized embeddings: rows 0..4095 = query tokens, 4096..20479 = doc tokens
__device__ __nv_bfloat16 g_emb[(size_t)N_TOK * DIM];

// ---------------------------------------------------------------------------
// PTX helpers (base sm_103 features only — tcgen05 unavailable: harness PTX
// targets compute_103, not compute_103a)
// ---------------------------------------------------------------------------
__device__ __forceinline__ void ldsm4(uint32_t& r0, uint32_t& r1,
                                      uint32_t& r2, uint32_t& r3, unsigned addr) {
    asm volatile("ldmatrix.sync.aligned.m8n8.x4.shared.b16 {%0,%1,%2,%3}, [%4];\n"
                 : "=r"(r0), "=r"(r1), "=r"(r2), "=r"(r3) : "r"(addr));
}
__device__ __forceinline__ void ldsm4t(uint32_t& r0, uint32_t& r1,
                                       uint32_t& r2, uint32_t& r3, unsigned addr) {
    asm volatile("ldmatrix.sync.aligned.m8n8.x4.trans.shared.b16 {%0,%1,%2,%3}, [%4];\n"
                 : "=r"(r0), "=r"(r1), "=r"(r2), "=r"(r3) : "r"(addr));
}
__device__ __forceinline__ void mma16816(float* c, const uint32_t* a,
                                         uint32_t b0, uint32_t b1) {
    asm volatile(
        "mma.sync.aligned.m16n8k16.row.col.f32.bf16.bf16.f32 "
        "{%0,%1,%2,%3}, {%4,%5,%6,%7}, {%8,%9}, {%0,%1,%2,%3};\n"
        : "+f"(c[0]), "+f"(c[1]), "+f"(c[2]), "+f"(c[3])
        : "r"(a[0]), "r"(a[1]), "r"(a[2]), "r"(a[3]), "r"(b0), "r"(b1));
}
__device__ __forceinline__ void cp_async16(unsigned saddr, const void* g) {
    asm volatile("cp.async.cg.shared.global [%0], [%1], 16;\n"
                 :: "r"(saddr), "l"(g) : "memory");
}
__device__ __forceinline__ void cp_commit() {
    asm volatile("cp.async.commit_group;\n" ::: "memory");
}
template <int N> __device__ __forceinline__ void cp_wait() {
    asm volatile("cp.async.wait_group %0;\n" :: "n"(N) : "memory");
}
__device__ __forceinline__ uint32_t smem_u32(const void* p) {
    uint32_t a;
    asm("{ .reg .u64 t; cvta.to.shared.u64 t, %1; cvt.u32.u64 %0, t; }"
        : "=r"(a) : "l"(p));
    return a;
}

// ---------------------------------------------------------------------------
// Kernel 1: projection + bias + L2 normalize via tensor cores (hi/lo bf16
// split: C = Ahi*Bhi + Ahi*Blo + Alo*Bhi, ~fp32 accuracy). Proven in R2.
// ---------------------------------------------------------------------------
#define KPAD 72
#define NPAD 136

__global__ __launch_bounds__(256, 2) void embed_kernel(
    const float* __restrict__ qh, const float* __restrict__ dh,
    const float* __restrict__ W, const float* __restrict__ bias)
{
    extern __shared__ char esm[];
    __nv_bfloat16* sAhi = (__nv_bfloat16*)esm;              // 128 x 72
    __nv_bfloat16* sAlo = sAhi + 128 * KPAD;
    __nv_bfloat16* sWhi = sAlo + 128 * KPAD;                // 64 x 136
    __nv_bfloat16* sWlo = sWhi + 64 * NPAD;

    const int tid  = threadIdx.x;
    const int lane = tid & 31, warp = tid >> 5;
    const int row0 = blockIdx.x * 128;
    const float* src = (row0 < N_QTOK) ? (qh + (size_t)row0 * HID)
                                       : (dh + (size_t)(row0 - N_QTOK) * HID);

    float acc[16][4];
#pragma unroll
    for (int nt = 0; nt < 16; nt++)
#pragma unroll
        for (int r = 0; r < 4; r++) acc[nt][r] = 0.f;

    const unsigned uAhi = smem_u32(sAhi);
    const unsigned uAlo = smem_u32(sAlo);
    const unsigned uWhi = smem_u32(sWhi);
    const unsigned uWlo = smem_u32(sWlo);

    const unsigned aoff =
        (unsigned)((warp * 16 + (lane & 15)) * KPAD + (lane >> 4) * 8) * 2;
    const int bk = (lane & 7) + ((lane >> 3) & 1) * 8;
    const int bn = (lane >> 4) * 8;

    for (int kc = 0; kc < 4; kc++) {
        const int k0 = kc * 64;
        __syncthreads();
#pragma unroll
        for (int j = 0; j < 8; j++) {
            int f = tid + j * 256, r = f >> 4, cv = f & 15;
            float4 v = *(const float4*)(src + (size_t)r * HID + k0 + cv * 4);
            __nv_bfloat16 h[4], l[4];
            float vv[4] = { v.x, v.y, v.z, v.w };
#pragma unroll
            for (int e = 0; e < 4; e++) {
                h[e] = __float2bfloat16(vv[e]);
                l[e] = __float2bfloat16(vv[e] - __bfloat162float(h[e]));
            }
            *(uint2*)&sAhi[r * KPAD + cv * 4] = *(uint2*)h;
            *(uint2*)&sAlo[r * KPAD + cv * 4] = *(uint2*)l;
        }
#pragma unroll
        for (int j = 0; j < 8; j++) {
            int f = tid + j * 256, r = f >> 5, cv = f & 31;
            float4 v = *(const float4*)(W + (size_t)(k0 + r) * DIM + cv * 4);
            __nv_bfloat16 h[4], l[4];
            float vv[4] = { v.x, v.y, v.z, v.w };
#pragma unroll
            for (int e = 0; e < 4; e++) {
                h[e] = __float2bfloat16(vv[e]);
                l[e] = __float2bfloat16(vv[e] - __bfloat162float(h[e]));
            }
            *(uint2*)&sWhi[r * NPAD + cv * 4] = *(uint2*)h;
            *(uint2*)&sWlo[r * NPAD + cv * 4] = *(uint2*)l;
        }
        __syncthreads();

#pragma unroll
        for (int ks = 0; ks < 4; ks++) {
            uint32_t ah[4], al[4];
            ldsm4(ah[0], ah[1], ah[2], ah[3], uAhi + aoff + ks * 32);
            ldsm4(al[0], al[1], al[2], al[3], uAlo + aoff + ks * 32);
            const unsigned brow = (unsigned)((ks * 16 + bk) * NPAD + bn) * 2;
#pragma unroll
            for (int ntp = 0; ntp < 8; ntp++) {
                uint32_t bh[4], bl[4];
                ldsm4t(bh[0], bh[1], bh[2], bh[3], uWhi + brow + ntp * 32);
                ldsm4t(bl[0], bl[1], bl[2], bl[3], uWlo + brow + ntp * 32);
                mma16816(acc[2 * ntp],     ah, bh[0], bh[1]);
                mma16816(acc[2 * ntp],     ah, bl[0], bl[1]);
                mma16816(acc[2 * ntp],     al, bh[0], bh[1]);
                mma16816(acc[2 * ntp + 1], ah, bh[2], bh[3]);
                mma16816(acc[2 * ntp + 1], ah, bl[2], bl[3]);
                mma16816(acc[2 * ntp + 1], al, bh[2], bh[3]);
            }
        }
    }

    const int cbase = (lane & 3) * 2;
    float ssA = 0.f, ssB = 0.f;
#pragma unroll
    for (int nt = 0; nt < 16; nt++) {
        float2 bv = *(const float2*)(bias + nt * 8 + cbase);
        acc[nt][0] += bv.x; acc[nt][1] += bv.y;
        acc[nt][2] += bv.x; acc[nt][3] += bv.y;
        ssA += acc[nt][0] * acc[nt][0] + acc[nt][1] * acc[nt][1];
        ssB += acc[nt][2] * acc[nt][2] + acc[nt][3] * acc[nt][3];
    }
    ssA += __shfl_xor_sync(0xffffffffu, ssA, 1);
    ssA += __shfl_xor_sync(0xffffffffu, ssA, 2);
    ssB += __shfl_xor_sync(0xffffffffu, ssB, 1);
    ssB += __shfl_xor_sync(0xffffffffu, ssB, 2);
    float invA = 1.f / fmaxf(sqrtf(ssA), 1e-12f);
    float invB = 1.f / fmaxf(sqrtf(ssB), 1e-12f);

    const int rA = row0 + warp * 16 + (lane >> 2);
    const int rB = rA + 8;
#pragma unroll
    for (int nt = 0; nt < 16; nt++) {
        __nv_bfloat162 vA, vB;
        vA.x = __float2bfloat16(acc[nt][0] * invA);
        vA.y = __float2bfloat16(acc[nt][1] * invA);
        vB.x = __float2bfloat16(acc[nt][2] * invB);
        vB.y = __float2bfloat16(acc[nt][3] * invB);
        *(__nv_bfloat162*)(g_emb + (size_t)rA * DIM + nt * 8 + cbase) = vA;
        *(__nv_bfloat162*)(g_emb + (size_t)rB * DIM + nt * 8 + cbase) = vB;
    }
}

// ---------------------------------------------------------------------------
// Kernel 2: fused similarity GEMM + max_t + sum_s (mma.sync bf16).
// Block = 256 thr / 8 warps as 4(M) x 2(N): warp tile 32 rows x 64 cols.
// Block tile M=128 (4 query batches) x N=128 (1 doc batch) x K=128.
// 16 doc batches per block; smem doc tiles double-buffered (cp.async).
// ldsm:mma = 6:16 per k-step (vs 4:8 in R2) -> shared pipe below MMA floor.
// Epilogue: in-warp row-max -> double-buffered smem red[] -> finalize for
// tile i-1 overlapped after the i-th data barrier. 2 syncthreads per tile.
// ---------------------------------------------------------------------------
#define DSTR 136

__global__ __launch_bounds__(256, 2) void sim_kernel(float* __restrict__ out)
{
    extern __shared__ char smem[];
    __nv_bfloat16* sQ = (__nv_bfloat16*)smem;              // 128 x 136
    __nv_bfloat16* sD = sQ + 128 * DSTR;                   // 2 x (128 x 136)
    float* red = (float*)(sD + 2 * 128 * DSTR);            // [2][8 warps][32]

    const int tid  = threadIdx.x;
    const int lane = tid & 31, warp = tid >> 5;
    const int wm = warp >> 1, wn = warp & 1;
    const int qb0 = blockIdx.y * 4;        // 4 query batches per CTA
    const int db0 = blockIdx.x * 16;       // 16 doc batches per CTA

    {   // load Q tile: 128 rows x 128 bf16
        const __nv_bfloat16* qsrc = g_emb + (size_t)qb0 * 32 * DIM;
#pragma unroll
        for (int j = 0; j < 8; j++) {
            int f = tid + j * 256, r = f >> 4, c8 = f & 15;
            *(uint4*)(sQ + r * DSTR + c8 * 8) =
                *(const uint4*)(qsrc + (size_t)r * DIM + c8 * 8);
        }
    }
    const unsigned uQ = smem_u32(sQ);
    const unsigned uD = smem_u32(sD);

    {   // prefetch doc tile 0 into buffer 0
        const __nv_bfloat16* dsrc = g_emb + (size_t)(N_QTOK + db0 * 128) * DIM;
#pragma unroll
        for (int j = 0; j < 8; j++) {
            int f = tid + j * 256, r = f >> 4, c8 = f & 15;
            cp_async16(uD + (unsigned)(r * DSTR + c8 * 8) * 2,
                       dsrc + (size_t)r * DIM + c8 * 8);
        }
        cp_commit();
    }

    // fragment addresses
    unsigned aoff[2];
#pragma unroll
    for (int mt = 0; mt < 2; mt++) {
        int row = wm * 32 + mt * 16 + (lane & 15);
        int col = (lane >> 4) * 8;
        aoff[mt] = uQ + (unsigned)(row * DSTR + col) * 2;
    }
    unsigned boff[4];
#pragma unroll
    for (int g = 0; g < 4; g++) {
        int row = wn * 64 + g * 16 + (lane & 7) + (lane >> 4) * 8;
        int col = ((lane >> 3) & 1) * 8;
        boff[g] = (unsigned)(row * DSTR + col) * 2;
    }

    for (int i = 0; i < 16; i++) {
        if (i + 1 < 16) {   // prefetch next doc tile
            const __nv_bfloat16* dsrc =
                g_emb + (size_t)(N_QTOK + (db0 + i + 1) * 128) * DIM;
            const unsigned dst = uD + (unsigned)((i + 1) & 1) * (128 * DSTR * 2);
#pragma unroll
            for (int j = 0; j < 8; j++) {
                int f = tid + j * 256, r = f >> 4, c8 = f & 15;
                cp_async16(dst + (unsigned)(r * DSTR + c8 * 8) * 2,
                           dsrc + (size_t)r * DIM + c8 * 8);
            }
            cp_commit();
            cp_wait<1>();
        } else {
            cp_wait<0>();
        }
        __syncthreads();   // S1: tile i data visible; prev readers done

        if (i >= 1 && tid < 128) {   // finalize tile i-1 (reads red[(i-1)&1])
            const int qb = tid >> 5, row = tid & 31;
            const float* rb = red + ((i - 1) & 1) * 256;
            float v = fmaxf(rb[(qb * 2) * 32 + row], rb[(qb * 2 + 1) * 32 + row]);
#pragma unroll
            for (int off = 16; off >= 1; off >>= 1)
                v += __shfl_xor_sync(0xffffffffu, v, off);
            if (lane == 0)
                out[(size_t)(qb0 + qb) * 128 + (db0 + i - 1)] = v;
        }

        float acc[2][8][4];
#pragma unroll
        for (int mt = 0; mt < 2; mt++)
#pragma unroll
            for (int j = 0; j < 8; j++)
#pragma unroll
                for (int r = 0; r < 4; r++) acc[mt][j][r] = 0.f;

        const unsigned dbase = uD + (unsigned)(i & 1) * (128 * DSTR * 2);
#pragma unroll
        for (int ks = 0; ks < 8; ks++) {
            uint32_t a[2][4], b[4][4];
            ldsm4(a[0][0], a[0][1], a[0][2], a[0][3], aoff[0] + ks * 32);
            ldsm4(a[1][0], a[1][1], a[1][2], a[1][3], aoff[1] + ks * 32);
#pragma unroll
            for (int g = 0; g < 4; g++)
                ldsm4(b[g][0], b[g][1], b[g][2], b[g][3],
                      dbase + boff[g] + ks * 32);
#pragma unroll
            for (int mt = 0; mt < 2; mt++)
#pragma unroll
                for (int j = 0; j < 8; j++)
                    mma16816(acc[mt][j], a[mt],
                             b[j >> 1][(j & 1) * 2], b[j >> 1][(j & 1) * 2 + 1]);
        }

        // in-warp row-max over this warp's 64 columns -> red[i&1]
        float* rw = red + (i & 1) * 256 + warp * 32;
#pragma unroll
        for (int mt = 0; mt < 2; mt++) {
#pragma unroll
            for (int h = 0; h < 2; h++) {
                float m = -3.4e38f;
#pragma unroll
                for (int j = 0; j < 8; j++)
                    m = fmaxf(m, fmaxf(acc[mt][j][2 * h], acc[mt][j][2 * h + 1]));
                m = fmaxf(m, __shfl_xor_sync(0xffffffffu, m, 1));
                m = fmaxf(m, __shfl_xor_sync(0xffffffffu, m, 2));
                if ((lane & 3) == 0)
                    rw[mt * 16 + h * 8 + (lane >> 2)] = m;
            }
        }
        __syncthreads();   // S2: red complete; MMA reads done -> buffer reusable
    }

    // tail: finalize tile 15 (red buffer 1; S2 already ordered it)
    if (tid < 128) {
        const int qb = tid >> 5, row = tid & 31;
        const float* rb = red + 256;
        float v = fmaxf(rb[(qb * 2) * 32 + row], rb[(qb * 2 + 1) * 32 + row]);
#pragma unroll
        for (int off = 16; off >= 1; off >>= 1)
            v += __shfl_xor_sync(0xffffffffu, v, off);
        if (lane == 0)
            out[(size_t)(qb0 + qb) * 128 + (db0 + 15)] = v;
    }
}

// ---------------------------------------------------------------------------
extern "C" void kernel_launch(void* const* d_in, const int* in_sizes, int n_in,
                              void* d_out, int out_size) {
    const float* qh   = (const float*)d_in[0];
    const float* dh   = (const float*)d_in[1];
    const float* W    = (const float*)d_in[2];
    const float* bias = (const float*)d_in[3];
    float* out = (float*)d_out;

    const int ESMEM = (128 * KPAD * 2 + 64 * NPAD * 2) * 2;     // 71680
    const int SSMEM = 3 * 128 * DSTR * 2 + 2 * 256 * 4;         // 106496
    cudaFuncSetAttribute(embed_kernel,
                         cudaFuncAttributeMaxDynamicSharedMemorySize, ESMEM);
    cudaFuncSetAttribute(sim_kernel,
                         cudaFuncAttributeMaxDynamicSharedMemorySize, SSMEM);

    embed_kernel<<<N_TOK / 128, 256, ESMEM>>>(qh, dh, W, bias);
    sim_kernel<<<dim3(8, 32), 256, SSMEM>>>(out);
}

// round 6
// speedup vs baseline: 2.3063x; 1.0829x over previous
#include <cuda_runtime.h>
#include <cuda_bf16.h>
#include <cstdint>
#include <cstddef>

#define N_QTOK 4096      // 128 query batches * 32 tokens
#define N_DTOK 16384     // 128 doc batches * 128 tokens
#define N_TOK  20480
#define DIM    128
#define HID    256

// bf16 normalized embeddings: rows 0..4095 = query tokens, 4096..20479 = doc tokens
__device__ __nv_bfloat16 g_emb[(size_t)N_TOK * DIM];

// ---------------------------------------------------------------------------
// PTX helpers (base sm_103 only — tcgen05 needs compute_103a virtual arch,
// which the harness does not use)
// ---------------------------------------------------------------------------
__device__ __forceinline__ void ldsm4(uint32_t& r0, uint32_t& r1,
                                      uint32_t& r2, uint32_t& r3, unsigned addr) {
    asm volatile("ldmatrix.sync.aligned.m8n8.x4.shared.b16 {%0,%1,%2,%3}, [%4];\n"
                 : "=r"(r0), "=r"(r1), "=r"(r2), "=r"(r3) : "r"(addr));
}
__device__ __forceinline__ void ldsm4t(uint32_t& r0, uint32_t& r1,
                                       uint32_t& r2, uint32_t& r3, unsigned addr) {
    asm volatile("ldmatrix.sync.aligned.m8n8.x4.trans.shared.b16 {%0,%1,%2,%3}, [%4];\n"
                 : "=r"(r0), "=r"(r1), "=r"(r2), "=r"(r3) : "r"(addr));
}
__device__ __forceinline__ void mma16816(float* c, const uint32_t* a,
                                         uint32_t b0, uint32_t b1) {
    asm volatile(
        "mma.sync.aligned.m16n8k16.row.col.f32.bf16.bf16.f32 "
        "{%0,%1,%2,%3}, {%4,%5,%6,%7}, {%8,%9}, {%0,%1,%2,%3};\n"
        : "+f"(c[0]), "+f"(c[1]), "+f"(c[2]), "+f"(c[3])
        : "r"(a[0]), "r"(a[1]), "r"(a[2]), "r"(a[3]), "r"(b0), "r"(b1));
}
__device__ __forceinline__ void cp_async16(unsigned saddr, const void* g) {
    asm volatile("cp.async.cg.shared.global [%0], [%1], 16;\n"
                 :: "r"(saddr), "l"(g) : "memory");
}
__device__ __forceinline__ void cp_commit() {
    asm volatile("cp.async.commit_group;\n" ::: "memory");
}
template <int N> __device__ __forceinline__ void cp_wait() {
    asm volatile("cp.async.wait_group %0;\n" :: "n"(N) : "memory");
}
__device__ __forceinline__ uint32_t smem_u32(const void* p) {
    uint32_t a;
    asm("{ .reg .u64 t; cvta.to.shared.u64 t, %1; cvt.u32.u64 %0, t; }"
        : "=r"(a) : "l"(p));
    return a;
}

// ---------------------------------------------------------------------------
// Kernel 1: projection + bias + L2 normalize (hi/lo bf16 split ~ fp32).
// Block 256 thr / 8 warps as 4(M) x 2(N): warp tile 32 rows x 64 cols.
// ldsm:mma = 12:48 per k-step -> LDS below MMA floor.
// ---------------------------------------------------------------------------
#define KPAD 72
#define NPAD 136

__global__ __launch_bounds__(256, 2) void embed_kernel(
    const float* __restrict__ qh, const float* __restrict__ dh,
    const float* __restrict__ W, const float* __restrict__ bias)
{
    extern __shared__ char esm[];
    __nv_bfloat16* sAhi = (__nv_bfloat16*)esm;              // 128 x 72
    __nv_bfloat16* sAlo = sAhi + 128 * KPAD;
    __nv_bfloat16* sWhi = sAlo + 128 * KPAD;                // 64 x 136
    __nv_bfloat16* sWlo = sWhi + 64 * NPAD;
    float* ssp = (float*)(sWlo + 64 * NPAD);                // [128][2]

    const int tid  = threadIdx.x;
    const int lane = tid & 31, warp = tid >> 5;
    const int wm = warp >> 1, wn = warp & 1;
    const int row0 = blockIdx.x * 128;
    const float* src = (row0 < N_QTOK) ? (qh + (size_t)row0 * HID)
                                       : (dh + (size_t)(row0 - N_QTOK) * HID);

    float acc[2][8][4];
#pragma unroll
    for (int mt = 0; mt < 2; mt++)
#pragma unroll
        for (int j = 0; j < 8; j++)
#pragma unroll
            for (int r = 0; r < 4; r++) acc[mt][j][r] = 0.f;

    const unsigned uAhi = smem_u32(sAhi);
    const unsigned uAlo = smem_u32(sAlo);
    const unsigned uWhi = smem_u32(sWhi);
    const unsigned uWlo = smem_u32(sWlo);

    unsigned aoff[2];
#pragma unroll
    for (int mt = 0; mt < 2; mt++)
        aoff[mt] = (unsigned)((wm * 32 + mt * 16 + (lane & 15)) * KPAD
                              + (lane >> 4) * 8) * 2;
    const int bk  = (lane & 7) + ((lane >> 3) & 1) * 8;
    const unsigned bnb = (unsigned)(wn * 64 + (lane >> 4) * 8) * 2;

    for (int kc = 0; kc < 4; kc++) {
        const int k0 = kc * 64;
        __syncthreads();
#pragma unroll
        for (int j = 0; j < 8; j++) {
            int f = tid + j * 256, r = f >> 4, cv = f & 15;
            float4 v = *(const float4*)(src + (size_t)r * HID + k0 + cv * 4);
            __nv_bfloat16 h[4], l[4];
            float vv[4] = { v.x, v.y, v.z, v.w };
#pragma unroll
            for (int e = 0; e < 4; e++) {
                h[e] = __float2bfloat16(vv[e]);
                l[e] = __float2bfloat16(vv[e] - __bfloat162float(h[e]));
            }
            *(uint2*)&sAhi[r * KPAD + cv * 4] = *(uint2*)h;
            *(uint2*)&sAlo[r * KPAD + cv * 4] = *(uint2*)l;
        }
#pragma unroll
        for (int j = 0; j < 8; j++) {
            int f = tid + j * 256, r = f >> 5, cv = f & 31;
            float4 v = *(const float4*)(W + (size_t)(k0 + r) * DIM + cv * 4);
            __nv_bfloat16 h[4], l[4];
            float vv[4] = { v.x, v.y, v.z, v.w };
#pragma unroll
            for (int e = 0; e < 4; e++) {
                h[e] = __float2bfloat16(vv[e]);
                l[e] = __float2bfloat16(vv[e] - __bfloat162float(h[e]));
            }
            *(uint2*)&sWhi[r * NPAD + cv * 4] = *(uint2*)h;
            *(uint2*)&sWlo[r * NPAD + cv * 4] = *(uint2*)l;
        }
        __syncthreads();

#pragma unroll
        for (int ks = 0; ks < 4; ks++) {
            uint32_t ah0[4], ah1[4], al0[4], al1[4];
            ldsm4(ah0[0], ah0[1], ah0[2], ah0[3], uAhi + aoff[0] + ks * 32);
            ldsm4(ah1[0], ah1[1], ah1[2], ah1[3], uAhi + aoff[1] + ks * 32);
            ldsm4(al0[0], al0[1], al0[2], al0[3], uAlo + aoff[0] + ks * 32);
            ldsm4(al1[0], al1[1], al1[2], al1[3], uAlo + aoff[1] + ks * 32);
            const unsigned brow = (unsigned)((ks * 16 + bk) * NPAD) * 2 + bnb;
#pragma unroll
            for (int ntp = 0; ntp < 4; ntp++) {
                uint32_t bh[4], bl[4];
                ldsm4t(bh[0], bh[1], bh[2], bh[3], uWhi + brow + ntp * 32);
                ldsm4t(bl[0], bl[1], bl[2], bl[3], uWlo + brow + ntp * 32);
                mma16816(acc[0][2 * ntp],     ah0, bh[0], bh[1]);
                mma16816(acc[0][2 * ntp],     ah0, bl[0], bl[1]);
                mma16816(acc[0][2 * ntp],     al0, bh[0], bh[1]);
                mma16816(acc[0][2 * ntp + 1], ah0, bh[2], bh[3]);
                mma16816(acc[0][2 * ntp + 1], ah0, bl[2], bl[3]);
                mma16816(acc[0][2 * ntp + 1], al0, bh[2], bh[3]);
                mma16816(acc[1][2 * ntp],     ah1, bh[0], bh[1]);
                mma16816(acc[1][2 * ntp],     ah1, bl[0], bl[1]);
                mma16816(acc[1][2 * ntp],     al1, bh[0], bh[1]);
                mma16816(acc[1][2 * ntp + 1], ah1, bh[2], bh[3]);
                mma16816(acc[1][2 * ntp + 1], ah1, bl[2], bl[3]);
                mma16816(acc[1][2 * ntp + 1], al1, bh[2], bh[3]);
            }
        }
    }

    // epilogue: bias, partial sum-of-squares per row-half (64 cols / warp)
    const int cbase = (lane & 3) * 2;
#pragma unroll
    for (int mt = 0; mt < 2; mt++) {
        float s0 = 0.f, s1 = 0.f;
#pragma unroll
        for (int j = 0; j < 8; j++) {
            float2 bv = *(const float2*)(bias + wn * 64 + j * 8 + cbase);
            acc[mt][j][0] += bv.x; acc[mt][j][1] += bv.y;
            acc[mt][j][2] += bv.x; acc[mt][j][3] += bv.y;
            s0 += acc[mt][j][0] * acc[mt][j][0] + acc[mt][j][1] * acc[mt][j][1];
            s1 += acc[mt][j][2] * acc[mt][j][2] + acc[mt][j][3] * acc[mt][j][3];
        }
        s0 += __shfl_xor_sync(0xffffffffu, s0, 1);
        s0 += __shfl_xor_sync(0xffffffffu, s0, 2);
        s1 += __shfl_xor_sync(0xffffffffu, s1, 1);
        s1 += __shfl_xor_sync(0xffffffffu, s1, 2);
        if ((lane & 3) == 0) {
            ssp[(wm * 32 + mt * 16 + (lane >> 2)) * 2 + wn] = s0;
            ssp[(wm * 32 + mt * 16 + 8 + (lane >> 2)) * 2 + wn] = s1;
        }
    }
    __syncthreads();
#pragma unroll
    for (int mt = 0; mt < 2; mt++) {
        const int r0 = wm * 32 + mt * 16 + (lane >> 2);
        const int r1 = r0 + 8;
        float inv0 = 1.f / fmaxf(sqrtf(ssp[r0 * 2] + ssp[r0 * 2 + 1]), 1e-12f);
        float inv1 = 1.f / fmaxf(sqrtf(ssp[r1 * 2] + ssp[r1 * 2 + 1]), 1e-12f);
#pragma unroll
        for (int j = 0; j < 8; j++) {
            __nv_bfloat162 vA, vB;
            vA.x = __float2bfloat16(acc[mt][j][0] * inv0);
            vA.y = __float2bfloat16(acc[mt][j][1] * inv0);
            vB.x = __float2bfloat16(acc[mt][j][2] * inv1);
            vB.y = __float2bfloat16(acc[mt][j][3] * inv1);
            *(__nv_bfloat162*)(g_emb + (size_t)(row0 + r0) * DIM
                               + wn * 64 + j * 8 + cbase) = vA;
            *(__nv_bfloat162*)(g_emb + (size_t)(row0 + r1) * DIM
                               + wn * 64 + j * 8 + cbase) = vB;
        }
    }
}

// ---------------------------------------------------------------------------
// Kernel 2: PERSISTENT fused similarity GEMM + max_t + sum_s.
// 4096 work units = (qg 0..31: 4 query batches) x (db 0..127: 1 doc batch).
// Grid = 2*num_SMs CTAs; CTA c owns units [c*4096/G, (c+1)*4096/G).
// Block 256 thr / 8 warps as 4(M) x 2(N); tile M=128 x N=128 x K=128.
// Doc tiles double-buffered via cp.async; epilogue red[] double-buffered,
// finalize of unit j-1 overlapped after the barrier of unit j.
// ---------------------------------------------------------------------------
#define DSTR 136

__global__ __launch_bounds__(256, 2) void sim_kernel(float* __restrict__ out)
{
    extern __shared__ char smem[];
    __nv_bfloat16* sQ = (__nv_bfloat16*)smem;              // 128 x 136
    __nv_bfloat16* sD = sQ + 128 * DSTR;                   // 2 x (128 x 136)
    float* red = (float*)(sD + 2 * 128 * DSTR);            // [2][8 warps][32]

    const int tid  = threadIdx.x;
    const int lane = tid & 31, warp = tid >> 5;
    const int wm = warp >> 1, wn = warp & 1;
    const unsigned G = gridDim.x, c = blockIdx.x;
    unsigned s = (4096u * c) / G;
    const unsigned e = (4096u * (c + 1)) / G;

    const unsigned uQ = smem_u32(sQ);
    const unsigned uD = smem_u32(sD);

    unsigned aoff[2];
#pragma unroll
    for (int mt = 0; mt < 2; mt++) {
        int row = wm * 32 + mt * 16 + (lane & 15);
        int col = (lane >> 4) * 8;
        aoff[mt] = uQ + (unsigned)(row * DSTR + col) * 2;
    }
    unsigned boff[4];
#pragma unroll
    for (int g = 0; g < 4; g++) {
        int row = wn * 64 + g * 16 + (lane & 7) + (lane >> 4) * 8;
        int col = ((lane >> 3) & 1) * 8;
        boff[g] = (unsigned)(row * DSTR + col) * 2;
    }

    while (s < e) {
        const unsigned qg = s >> 7;
        const unsigned seg_e = min(e, (qg + 1) << 7);
        const int n = (int)(seg_e - s);
        const unsigned qb0 = qg * 4;
        const unsigned db_base = s & 127;

        {   // load Q tile for this segment (plain LDG->STS; L2-resident)
            const __nv_bfloat16* qsrc = g_emb + (size_t)qg * 128 * DIM;
#pragma unroll
            for (int j = 0; j < 8; j++) {
                int f = tid + j * 256, r = f >> 4, c8 = f & 15;
                *(uint4*)(sQ + r * DSTR + c8 * 8) =
                    *(const uint4*)(qsrc + (size_t)r * DIM + c8 * 8);
            }
        }
        {   // prefetch first doc tile of segment into buffer 0
            const __nv_bfloat16* dsrc =
                g_emb + (size_t)(N_QTOK + db_base * 128) * DIM;
#pragma unroll
            for (int j = 0; j < 8; j++) {
                int f = tid + j * 256, r = f >> 4, c8 = f & 15;
                cp_async16(uD + (unsigned)(r * DSTR + c8 * 8) * 2,
                           dsrc + (size_t)r * DIM + c8 * 8);
            }
            cp_commit();
        }

        for (int j = 0; j < n; j++) {
            if (j + 1 < n) {   // prefetch next doc tile
                const __nv_bfloat16* dsrc =
                    g_emb + (size_t)(N_QTOK + (db_base + j + 1) * 128) * DIM;
                const unsigned dst =
                    uD + (unsigned)((j + 1) & 1) * (128 * DSTR * 2);
#pragma unroll
                for (int t = 0; t < 8; t++) {
                    int f = tid + t * 256, r = f >> 4, c8 = f & 15;
                    cp_async16(dst + (unsigned)(r * DSTR + c8 * 8) * 2,
                               dsrc + (size_t)r * DIM + c8 * 8);
                }
                cp_commit();
                cp_wait<1>();
            } else {
                cp_wait<0>();
            }
            __syncthreads();   // S1: tile j data + Q visible

            if (j >= 1 && tid < 128) {   // finalize unit j-1
                const int qb = tid >> 5, row = tid & 31;
                const float* rb = red + ((j - 1) & 1) * 256;
                float v = fmaxf(rb[(qb * 2) * 32 + row],
                                rb[(qb * 2 + 1) * 32 + row]);
#pragma unroll
                for (int off = 16; off >= 1; off >>= 1)
                    v += __shfl_xor_sync(0xffffffffu, v, off);
                if (lane == 0)
                    out[(size_t)(qb0 + qb) * 128 + (db_base + j - 1)] = v;
            }

            float acc[2][8][4];
#pragma unroll
            for (int mt = 0; mt < 2; mt++)
#pragma unroll
                for (int t = 0; t < 8; t++)
#pragma unroll
                    for (int r = 0; r < 4; r++) acc[mt][t][r] = 0.f;

            const unsigned dbase = uD + (unsigned)(j & 1) * (128 * DSTR * 2);
#pragma unroll
            for (int ks = 0; ks < 8; ks++) {
                uint32_t a[2][4], b[4][4];
                ldsm4(a[0][0], a[0][1], a[0][2], a[0][3], aoff[0] + ks * 32);
                ldsm4(a[1][0], a[1][1], a[1][2], a[1][3], aoff[1] + ks * 32);
#pragma unroll
                for (int g = 0; g < 4; g++)
                    ldsm4(b[g][0], b[g][1], b[g][2], b[g][3],
                          dbase + boff[g] + ks * 32);
#pragma unroll
                for (int mt = 0; mt < 2; mt++)
#pragma unroll
                    for (int t = 0; t < 8; t++)
                        mma16816(acc[mt][t], a[mt],
                                 b[t >> 1][(t & 1) * 2],
                                 b[t >> 1][(t & 1) * 2 + 1]);
            }

            // in-warp row-max over this warp's 64 columns -> red[j&1]
            float* rw = red + (j & 1) * 256 + warp * 32;
#pragma unroll
            for (int mt = 0; mt < 2; mt++) {
#pragma unroll
                for (int h = 0; h < 2; h++) {
                    float m = -3.4e38f;
#pragma unroll
                    for (int t = 0; t < 8; t++)
                        m = fmaxf(m, fmaxf(acc[mt][t][2 * h],
                                           acc[mt][t][2 * h + 1]));
                    m = fmaxf(m, __shfl_xor_sync(0xffffffffu, m, 1));
                    m = fmaxf(m, __shfl_xor_sync(0xffffffffu, m, 2));
                    if ((lane & 3) == 0)
                        rw[mt * 16 + h * 8 + (lane >> 2)] = m;
                }
            }
            __syncthreads();   // S2: red complete; buffers reusable
        }

        // tail: finalize last unit of segment
        if (tid < 128) {
            const int qb = tid >> 5, row = tid & 31;
            const float* rb = red + ((n - 1) & 1) * 256;
            float v = fmaxf(rb[(qb * 2) * 32 + row],
                            rb[(qb * 2 + 1) * 32 + row]);
#pragma unroll
            for (int off = 16; off >= 1; off >>= 1)
                v += __shfl_xor_sync(0xffffffffu, v, off);
            if (lane == 0)
                out[(size_t)(qb0 + qb) * 128 + (db_base + n - 1)] = v;
        }
        __syncthreads();   // protect red[] before next segment writes
        s = seg_e;
    }
}

// ---------------------------------------------------------------------------
extern "C" void kernel_launch(void* const* d_in, const int* in_sizes, int n_in,
                              void* d_out, int out_size) {
    const float* qh   = (const float*)d_in[0];
    const float* dh   = (const float*)d_in[1];
    const float* W    = (const float*)d_in[2];
    const float* bias = (const float*)d_in[3];
    float* out = (float*)d_out;

    int sms = 148;
    cudaDeviceGetAttribute(&sms, cudaDevAttrMultiProcessorCount, 0);
    const int G = 2 * sms;

    const int ESMEM = (128 * KPAD * 2 + 64 * NPAD * 2) * 2 + 128 * 2 * 4; // 72704
    const int SSMEM = 3 * 128 * DSTR * 2 + 2 * 256 * 4;                   // 106496
    cudaFuncSetAttribute(embed_kernel,
                         cudaFuncAttributeMaxDynamicSharedMemorySize, ESMEM);
    cudaFuncSetAttribute(sim_kernel,
                         cudaFuncAttributeMaxDynamicSharedMemorySize, SSMEM);

    embed_kernel<<<N_TOK / 128, 256, ESMEM>>>(qh, dh, W, bias);
    sim_kernel<<<G, 256, SSMEM>>>(out);
}

// round 7
// speedup vs baseline: 2.3083x; 1.0009x over previous
#include <cuda_runtime.h>
#include <cuda_bf16.h>
#include <cstdint>
#include <cstddef>

#define N_QTOK 4096      // 128 query batches * 32 tokens
#define N_DTOK 16384     // 128 doc batches * 128 tokens
#define N_TOK  20480
#define DIM    128
#define HID    256
#define N_ETILE 640      // 20480 / 32 rows per embed tile

// bf16 normalized embeddings: rows 0..4095 = query tokens, 4096..20479 = doc tokens
__device__ __align__(16) __nv_bfloat16 g_emb[(size_t)N_TOK * DIM];
// preconverted W hi/lo (bf16 split of fp32 W)
__device__ __align__(16) __nv_bfloat16 g_Whi[HID * DIM];
__device__ __align__(16) __nv_bfloat16 g_Wlo[HID * DIM];
__device__ unsigned g_ctr;   // embed work-steal counter (reset by wconv_kernel)

// ---------------------------------------------------------------------------
// PTX helpers (base sm_103 only — tcgen05 needs compute_103a virtual arch,
// which the harness does not use)
// ---------------------------------------------------------------------------
__device__ __forceinline__ void ldsm4(uint32_t& r0, uint32_t& r1,
                                      uint32_t& r2, uint32_t& r3, unsigned addr) {
    asm volatile("ldmatrix.sync.aligned.m8n8.x4.shared.b16 {%0,%1,%2,%3}, [%4];\n"
                 : "=r"(r0), "=r"(r1), "=r"(r2), "=r"(r3) : "r"(addr));
}
__device__ __forceinline__ void ldsm4t(uint32_t& r0, uint32_t& r1,
                                       uint32_t& r2, uint32_t& r3, unsigned addr) {
    asm volatile("ldmatrix.sync.aligned.m8n8.x4.trans.shared.b16 {%0,%1,%2,%3}, [%4];\n"
                 : "=r"(r0), "=r"(r1), "=r"(r2), "=r"(r3) : "r"(addr));
}
__device__ __forceinline__ void mma16816(float* c, const uint32_t* a,
                                         uint32_t b0, uint32_t b1) {
    asm volatile(
        "mma.sync.aligned.m16n8k16.row.col.f32.bf16.bf16.f32 "
        "{%0,%1,%2,%3}, {%4,%5,%6,%7}, {%8,%9}, {%0,%1,%2,%3};\n"
        : "+f"(c[0]), "+f"(c[1]), "+f"(c[2]), "+f"(c[3])
        : "r"(a[0]), "r"(a[1]), "r"(a[2]), "r"(a[3]), "r"(b0), "r"(b1));
}
__device__ __forceinline__ void cp_async16(unsigned saddr, const void* g) {
    asm volatile("cp.async.cg.shared.global [%0], [%1], 16;\n"
                 :: "r"(saddr), "l"(g) : "memory");
}
__device__ __forceinline__ void cp_commit() {
    asm volatile("cp.async.commit_group;\n" ::: "memory");
}
template <int N> __device__ __forceinline__ void cp_wait() {
    asm volatile("cp.async.wait_group %0;\n" :: "n"(N) : "memory");
}
__device__ __forceinline__ uint32_t smem_u32(const void* p) {
    uint32_t a;
    asm("{ .reg .u64 t; cvta.to.shared.u64 t, %1; cvt.u32.u64 %0, t; }"
        : "=r"(a) : "l"(p));
    return a;
}

// ---------------------------------------------------------------------------
// Kernel 0: convert W (fp32 256x128) -> hi/lo bf16 once; reset steal counter.
// ---------------------------------------------------------------------------
__global__ void wconv_kernel(const float* __restrict__ W) {
    if (blockIdx.x == 0 && threadIdx.x == 0) g_ctr = 0u;
    const int idx = blockIdx.x * 256 + threadIdx.x;     // 8192 float4s
    float4 v = ((const float4*)W)[idx];
    float vv[4] = { v.x, v.y, v.z, v.w };
    __nv_bfloat16 h[4], l[4];
#pragma unroll
    for (int e = 0; e < 4; e++) {
        h[e] = __float2bfloat16(vv[e]);
        l[e] = __float2bfloat16(vv[e] - __bfloat162float(h[e]));
    }
    *(uint2*)&g_Whi[idx * 4] = *(uint2*)h;
    *(uint2*)&g_Wlo[idx * 4] = *(uint2*)l;
}

// ---------------------------------------------------------------------------
// Kernel 1: projection + bias + L2 normalize (hi/lo bf16 split ~ fp32).
// Work-stealing: 640 tiles of 32 rows; grid = 4*SMs persistent workers.
// Block 128 thr / 4 warps as 2(M) x 2(N): warp tile 16 rows x 64 cols.
// W streamed preconverted via cp.async (no per-CTA conversion).
// ---------------------------------------------------------------------------
#define KPAD 72
#define NPAD 136

__global__ __launch_bounds__(128, 4) void embed_kernel(
    const float* __restrict__ qh, const float* __restrict__ dh,
    const float* __restrict__ bias)
{
    extern __shared__ char esm[];
    __nv_bfloat16* sAhi = (__nv_bfloat16*)esm;              // 32 x 72
    __nv_bfloat16* sAlo = sAhi + 32 * KPAD;
    __nv_bfloat16* sWhi = sAlo + 32 * KPAD;                 // 64 x 136
    __nv_bfloat16* sWlo = sWhi + 64 * NPAD;
    float* ssp = (float*)(sWlo + 64 * NPAD);                // [32][2]
    __shared__ unsigned s_t;

    const int tid  = threadIdx.x;
    const int lane = tid & 31, warp = tid >> 5;
    const int wm = warp >> 1, wn = warp & 1;

    const unsigned uAhi = smem_u32(sAhi);
    const unsigned uAlo = smem_u32(sAlo);
    const unsigned uWhi = smem_u32(sWhi);
    const unsigned uWlo = smem_u32(sWlo);

    const unsigned aoff =
        (unsigned)((wm * 16 + (lane & 15)) * KPAD + (lane >> 4) * 8) * 2;
    const int bk  = (lane & 7) + ((lane >> 3) & 1) * 8;
    const unsigned bnb = (unsigned)(wn * 64 + (lane >> 4) * 8) * 2;
    const int cbase = (lane & 3) * 2;

    for (;;) {
        __syncthreads();                       // prior tile smem reads done
        if (tid == 0) s_t = atomicAdd(&g_ctr, 1u);
        __syncthreads();
        const unsigned t = s_t;
        if (t >= N_ETILE) break;

        const int row0 = (int)t * 32;
        const float* src = (row0 < N_QTOK)
            ? (qh + (size_t)row0 * HID)
            : (dh + (size_t)(row0 - N_QTOK) * HID);

        float acc[8][4];
#pragma unroll
        for (int j = 0; j < 8; j++)
#pragma unroll
            for (int r = 0; r < 4; r++) acc[j][r] = 0.f;

        for (int kc = 0; kc < 4; kc++) {
            const int k0 = kc * 64;
            if (kc) __syncthreads();           // prior kc ldsm reads done

            // stream preconverted W chunk (64 k x 128 n, hi+lo) via cp.async
#pragma unroll
            for (int j = 0; j < 8; j++) {
                int f = tid + j * 128, r = f >> 4, c8 = f & 15;
                cp_async16(uWhi + (unsigned)(r * NPAD + c8 * 8) * 2,
                           g_Whi + (size_t)(k0 + r) * DIM + c8 * 8);
            }
#pragma unroll
            for (int j = 0; j < 8; j++) {
                int f = tid + j * 128, r = f >> 4, c8 = f & 15;
                cp_async16(uWlo + (unsigned)(r * NPAD + c8 * 8) * 2,
                           g_Wlo + (size_t)(k0 + r) * DIM + c8 * 8);
            }
            cp_commit();

            // A chunk: 32 rows x 64 k fp32 -> hi/lo bf16 (4 float4 / thread)
#pragma unroll
            for (int j = 0; j < 4; j++) {
                int f = tid + j * 128, r = f >> 4, cv = f & 15;
                float4 v = *(const float4*)(src + (size_t)r * HID + k0 + cv * 4);
                float vv[4] = { v.x, v.y, v.z, v.w };
                __nv_bfloat16 h[4], l[4];
#pragma unroll
                for (int e = 0; e < 4; e++) {
                    h[e] = __float2bfloat16(vv[e]);
                    l[e] = __float2bfloat16(vv[e] - __bfloat162float(h[e]));
                }
                *(uint2*)&sAhi[r * KPAD + cv * 4] = *(uint2*)h;
                *(uint2*)&sAlo[r * KPAD + cv * 4] = *(uint2*)l;
            }
            cp_wait<0>();
            __syncthreads();

#pragma unroll
            for (int ks = 0; ks < 4; ks++) {
                uint32_t ah[4], al[4];
                ldsm4(ah[0], ah[1], ah[2], ah[3], uAhi + aoff + ks * 32);
                ldsm4(al[0], al[1], al[2], al[3], uAlo + aoff + ks * 32);
                const unsigned brow = (unsigned)((ks * 16 + bk) * NPAD) * 2 + bnb;
#pragma unroll
                for (int ntp = 0; ntp < 4; ntp++) {
                    uint32_t bh[4], bl[4];
                    ldsm4t(bh[0], bh[1], bh[2], bh[3], uWhi + brow + ntp * 32);
                    ldsm4t(bl[0], bl[1], bl[2], bl[3], uWlo + brow + ntp * 32);
                    mma16816(acc[2 * ntp],     ah, bh[0], bh[1]);
                    mma16816(acc[2 * ntp],     ah, bl[0], bl[1]);
                    mma16816(acc[2 * ntp],     al, bh[0], bh[1]);
                    mma16816(acc[2 * ntp + 1], ah, bh[2], bh[3]);
                    mma16816(acc[2 * ntp + 1], ah, bl[2], bl[3]);
                    mma16816(acc[2 * ntp + 1], al, bh[2], bh[3]);
                }
            }
        }

        // epilogue: bias + partial sum-of-squares (this warp's 64 cols)
        float s0 = 0.f, s1 = 0.f;
#pragma unroll
        for (int j = 0; j < 8; j++) {
            float2 bv = *(const float2*)(bias + wn * 64 + j * 8 + cbase);
            acc[j][0] += bv.x; acc[j][1] += bv.y;
            acc[j][2] += bv.x; acc[j][3] += bv.y;
            s0 += acc[j][0] * acc[j][0] + acc[j][1] * acc[j][1];
            s1 += acc[j][2] * acc[j][2] + acc[j][3] * acc[j][3];
        }
        s0 += __shfl_xor_sync(0xffffffffu, s0, 1);
        s0 += __shfl_xor_sync(0xffffffffu, s0, 2);
        s1 += __shfl_xor_sync(0xffffffffu, s1, 1);
        s1 += __shfl_xor_sync(0xffffffffu, s1, 2);
        const int r0 = wm * 16 + (lane >> 2);
        const int r1 = r0 + 8;
        if ((lane & 3) == 0) {
            ssp[r0 * 2 + wn] = s0;
            ssp[r1 * 2 + wn] = s1;
        }
        __syncthreads();
        float inv0 = 1.f / fmaxf(sqrtf(ssp[r0 * 2] + ssp[r0 * 2 + 1]), 1e-12f);
        float inv1 = 1.f / fmaxf(sqrtf(ssp[r1 * 2] + ssp[r1 * 2 + 1]), 1e-12f);
#pragma unroll
        for (int j = 0; j < 8; j++) {
            __nv_bfloat162 vA, vB;
            vA.x = __float2bfloat16(acc[j][0] * inv0);
            vA.y = __float2bfloat16(acc[j][1] * inv0);
            vB.x = __float2bfloat16(acc[j][2] * inv1);
            vB.y = __float2bfloat16(acc[j][3] * inv1);
            *(__nv_bfloat162*)(g_emb + (size_t)(row0 + r0) * DIM
                               + wn * 64 + j * 8 + cbase) = vA;
            *(__nv_bfloat162*)(g_emb + (size_t)(row0 + r1) * DIM
                               + wn * 64 + j * 8 + cbase) = vB;
        }
    }
}

// ---------------------------------------------------------------------------
// Kernel 2: PERSISTENT fused similarity GEMM + max_t + sum_s (unchanged R6).
// ---------------------------------------------------------------------------
#define DSTR 136

__global__ __launch_bounds__(256, 2) void sim_kernel(float* __restrict__ out)
{
    extern __shared__ char smem[];
    __nv_bfloat16* sQ = (__nv_bfloat16*)smem;              // 128 x 136
    __nv_bfloat16* sD = sQ + 128 * DSTR;                   // 2 x (128 x 136)
    float* red = (float*)(sD + 2 * 128 * DSTR);            // [2][8 warps][32]

    const int tid  = threadIdx.x;
    const int lane = tid & 31, warp = tid >> 5;
    const int wm = warp >> 1, wn = warp & 1;
    const unsigned G = gridDim.x, c = blockIdx.x;
    unsigned s = (4096u * c) / G;
    const unsigned e = (4096u * (c + 1)) / G;

    const unsigned uQ = smem_u32(sQ);
    const unsigned uD = smem_u32(sD);

    unsigned aoff[2];
#pragma unroll
    for (int mt = 0; mt < 2; mt++) {
        int row = wm * 32 + mt * 16 + (lane & 15);
        int col = (lane >> 4) * 8;
        aoff[mt] = uQ + (unsigned)(row * DSTR + col) * 2;
    }
    unsigned boff[4];
#pragma unroll
    for (int g = 0; g < 4; g++) {
        int row = wn * 64 + g * 16 + (lane & 7) + (lane >> 4) * 8;
        int col = ((lane >> 3) & 1) * 8;
        boff[g] = (unsigned)(row * DSTR + col) * 2;
    }

    while (s < e) {
        const unsigned qg = s >> 7;
        const unsigned seg_e = min(e, (qg + 1) << 7);
        const int n = (int)(seg_e - s);
        const unsigned qb0 = qg * 4;
        const unsigned db_base = s & 127;

        {   // load Q tile for this segment
            const __nv_bfloat16* qsrc = g_emb + (size_t)qg * 128 * DIM;
#pragma unroll
            for (int j = 0; j < 8; j++) {
                int f = tid + j * 256, r = f >> 4, c8 = f & 15;
                *(uint4*)(sQ + r * DSTR + c8 * 8) =
                    *(const uint4*)(qsrc + (size_t)r * DIM + c8 * 8);
            }
        }
        {   // prefetch first doc tile of segment into buffer 0
            const __nv_bfloat16* dsrc =
                g_emb + (size_t)(N_QTOK + db_base * 128) * DIM;
#pragma unroll
            for (int j = 0; j < 8; j++) {
                int f = tid + j * 256, r = f >> 4, c8 = f & 15;
                cp_async16(uD + (unsigned)(r * DSTR + c8 * 8) * 2,
                           dsrc + (size_t)r * DIM + c8 * 8);
            }
            cp_commit();
        }

        for (int j = 0; j < n; j++) {
            if (j + 1 < n) {
                const __nv_bfloat16* dsrc =
                    g_emb + (size_t)(N_QTOK + (db_base + j + 1) * 128) * DIM;
                const unsigned dst =
                    uD + (unsigned)((j + 1) & 1) * (128 * DSTR * 2);
#pragma unroll
                for (int t = 0; t < 8; t++) {
                    int f = tid + t * 256, r = f >> 4, c8 = f & 15;
                    cp_async16(dst + (unsigned)(r * DSTR + c8 * 8) * 2,
                               dsrc + (size_t)r * DIM + c8 * 8);
                }
                cp_commit();
                cp_wait<1>();
            } else {
                cp_wait<0>();
            }
            __syncthreads();   // S1: tile j data + Q visible

            if (j >= 1 && tid < 128) {   // finalize unit j-1
                const int qb = tid >> 5, row = tid & 31;
                const float* rb = red + ((j - 1) & 1) * 256;
                float v = fmaxf(rb[(qb * 2) * 32 + row],
                                rb[(qb * 2 + 1) * 32 + row]);
#pragma unroll
                for (int off = 16; off >= 1; off >>= 1)
                    v += __shfl_xor_sync(0xffffffffu, v, off);
                if (lane == 0)
                    out[(size_t)(qb0 + qb) * 128 + (db_base + j - 1)] = v;
            }

            float acc[2][8][4];
#pragma unroll
            for (int mt = 0; mt < 2; mt++)
#pragma unroll
                for (int t = 0; t < 8; t++)
#pragma unroll
                    for (int r = 0; r < 4; r++) acc[mt][t][r] = 0.f;

            const unsigned dbase = uD + (unsigned)(j & 1) * (128 * DSTR * 2);
#pragma unroll
            for (int ks = 0; ks < 8; ks++) {
                uint32_t a[2][4], b[4][4];
                ldsm4(a[0][0], a[0][1], a[0][2], a[0][3], aoff[0] + ks * 32);
                ldsm4(a[1][0], a[1][1], a[1][2], a[1][3], aoff[1] + ks * 32);
#pragma unroll
                for (int g = 0; g < 4; g++)
                    ldsm4(b[g][0], b[g][1], b[g][2], b[g][3],
                          dbase + boff[g] + ks * 32);
#pragma unroll
                for (int mt = 0; mt < 2; mt++)
#pragma unroll
                    for (int t = 0; t < 8; t++)
                        mma16816(acc[mt][t], a[mt],
                                 b[t >> 1][(t & 1) * 2],
                                 b[t >> 1][(t & 1) * 2 + 1]);
            }

            // in-warp row-max over this warp's 64 columns -> red[j&1]
            float* rw = red + (j & 1) * 256 + warp * 32;
#pragma unroll
            for (int mt = 0; mt < 2; mt++) {
#pragma unroll
                for (int h = 0; h < 2; h++) {
                    float m = -3.4e38f;
#pragma unroll
                    for (int t = 0; t < 8; t++)
                        m = fmaxf(m, fmaxf(acc[mt][t][2 * h],
                                           acc[mt][t][2 * h + 1]));
                    m = fmaxf(m, __shfl_xor_sync(0xffffffffu, m, 1));
                    m = fmaxf(m, __shfl_xor_sync(0xffffffffu, m, 2));
                    if ((lane & 3) == 0)
                        rw[mt * 16 + h * 8 + (lane >> 2)] = m;
                }
            }
            __syncthreads();   // S2: red complete; buffers reusable
        }

        // tail: finalize last unit of segment
        if (tid < 128) {
            const int qb = tid >> 5, row = tid & 31;
            const float* rb = red + ((n - 1) & 1) * 256;
            float v = fmaxf(rb[(qb * 2) * 32 + row],
                            rb[(qb * 2 + 1) * 32 + row]);
#pragma unroll
            for (int off = 16; off >= 1; off >>= 1)
                v += __shfl_xor_sync(0xffffffffu, v, off);
            if (lane == 0)
                out[(size_t)(qb0 + qb) * 128 + (db_base + n - 1)] = v;
        }
        __syncthreads();
        s = seg_e;
    }
}

// ---------------------------------------------------------------------------
extern "C" void kernel_launch(void* const* d_in, const int* in_sizes, int n_in,
                              void* d_out, int out_size) {
    const float* qh   = (const float*)d_in[0];
    const float* dh   = (const float*)d_in[1];
    const float* W    = (const float*)d_in[2];
    const float* bias = (const float*)d_in[3];
    float* out = (float*)d_out;

    int sms = 148;
    cudaDeviceGetAttribute(&sms, cudaDevAttrMultiProcessorCount, 0);

    const int ESMEM = 2 * (32 * KPAD * 2) + 2 * (64 * NPAD * 2) + 32 * 2 * 4; // 44288
    const int SSMEM = 3 * 128 * DSTR * 2 + 2 * 256 * 4;                       // 106496
    cudaFuncSetAttribute(embed_kernel,
                         cudaFuncAttributeMaxDynamicSharedMemorySize, ESMEM);
    cudaFuncSetAttribute(sim_kernel,
                         cudaFuncAttributeMaxDynamicSharedMemorySize, SSMEM);

    wconv_kernel<<<32, 256>>>(W);
    embed_kernel<<<4 * sms, 128, ESMEM>>>(qh, dh, bias);
    sim_kernel<<<2 * sms, 256, SSMEM>>>(out);
}